// round 11
// baseline (speedup 1.0000x reference)
#include <cuda_runtime.h>
#include <stdint.h>

#define NANCH 8732
#define NCLS 21
#define TOPK 200
#define CONF_TH 0.01f
#define NMS_TH 0.045f
#define MAXB 128
#define CANDCAP 2048u
#define NTASKMAX (MAXB * (NCLS - 1))
#define T0BITS 0x3E000000u    // 0.125f
#define NBLK 35               // ceil(8732/256) anchor-blocks per image
#define LCAP 64               // per-CTA per-class smem list capacity

// Scratch (no device allocs allowed):
__device__ unsigned long long g_cand[(size_t)NTASKMAX * CANDCAP];     // per-task lists
__device__ unsigned g_ccnt[NTASKMAX];                                 // counts (zero-init; B resets)
__device__ unsigned g_fb[(size_t)NTASKMAX * NANCH];                   // fallback scratch

// ---------------------------------------------------------------------------
// Kernel A: softmax + smem-aggregated candidate append (e_c >= 0.1249*sum,
// a strict superset of p >= 0.125; exact p bits stored). No box decode here.
// Grid: (NBLK, B). Flush = 1 global atomic per class per CTA.
// ---------------------------------------------------------------------------
__global__ void __launch_bounds__(256) softmax_cand_kernel(
        const float* __restrict__ conf) {
    __shared__ float sc[256 * NCLS];                         // 21504 B
    __shared__ unsigned long long slist[NCLS - 1][LCAP];     // 10240 B
    __shared__ unsigned scnt_s[NCLS - 1];

    int b = blockIdx.y;
    int n0 = blockIdx.x * 256;
    int n = n0 + threadIdx.x;
    int tid = threadIdx.x;

    if (tid < NCLS - 1) scnt_s[tid] = 0u;

    int nanch_here = min(256, NANCH - n0);
    int navail = nanch_here * NCLS;
    size_t gbase = ((size_t)b * NANCH + n0) * NCLS;
    for (int i = tid; i < navail; i += 256)
        sc[i] = conf[gbase + i];
    __syncthreads();

    if (n < NANCH) {
        float v[NCLS];
        float mx = -1e30f;
#pragma unroll
        for (int c = 0; c < NCLS; c++) { v[c] = sc[tid * NCLS + c]; mx = fmaxf(mx, v[c]); }
        float s = 0.0f;
#pragma unroll
        for (int c = 0; c < NCLS; c++) { v[c] = expf(v[c] - mx); s += v[c]; }
        float inv = 1.0f / s;
        float Ts = 0.1249f * s;            // margin 8e-4 >> fp rounding

        unsigned enc = (unsigned)(~n);
#pragma unroll
        for (int c = 1; c < NCLS; c++) {
            if (v[c] >= Ts) {
                float p = v[c] * inv;      // exact score bits
                unsigned long long key =
                    ((unsigned long long)__float_as_uint(p) << 32) | enc;
                unsigned pos = atomicAdd(&scnt_s[c - 1], 1u);
                if (pos < LCAP) {
                    slist[c - 1][pos] = key;
                } else {                   // spill (≈never): direct global
                    int task = b * (NCLS - 1) + (c - 1);
                    unsigned gp = atomicAdd(&g_ccnt[task], 1u);
                    if (gp < CANDCAP) g_cand[(size_t)task * CANDCAP + gp] = key;
                }
            }
        }
    }
    __syncthreads();

    int lane = tid & 31, wrp = tid >> 5;
    for (int cl = wrp; cl < NCLS - 1; cl += 8) {
        unsigned cnt = min(scnt_s[cl], (unsigned)LCAP);
        int task = b * (NCLS - 1) + cl;
        unsigned basep = 0u;
        if (lane == 0 && cnt) basep = atomicAdd(&g_ccnt[task], cnt);
        basep = __shfl_sync(0xffffffffu, basep, 0);
        for (unsigned i = lane; i < cnt; i += 32) {
            unsigned gp = basep + i;
            if (gp < CANDCAP) g_cand[(size_t)task * CANDCAP + gp] = slist[cl][i];
        }
    }
}

// ---------------------------------------------------------------------------
// Kernel B: ONE task per CTA. Load cand list (fallback: lean recompute +
// adaptive collect), 3-pass radix select (bits [26:19],[18:11],[10:3];
// bits[31:27]=00111 for p in (0.01,1]), exact 256-key bitonic sort,
// ON-DEMAND box decode at fetch, then warps 1-7 EXIT and warp 0 runs the
// register/shfl NMS + pack. Resets g_ccnt[task] for the next graph replay.
// ---------------------------------------------------------------------------
__global__ void __launch_bounds__(256) select_nms_kernel(
        const float* __restrict__ conf,
        const float* __restrict__ loc,
        const float* __restrict__ anchors,
        float* __restrict__ out) {
    int task = blockIdx.x;
    int b = task / (NCLS - 1);
    int c = task % (NCLS - 1);            // 0..19 -> class c+1
    int tid = threadIdx.x;
    int lane = tid & 31, wrp = tid >> 5;

    __shared__ __align__(16) unsigned long long cand[CANDCAP];   // 16384 B
    __shared__ __align__(16) unsigned long long skey[256];       // 2048 B
    __shared__ __align__(16) unsigned shist[256];                // 1024 B
    __shared__ unsigned k_sh, bin_sh, ccnt, scnt, cc_sh;

    // overlay on cand (dead after sort): 6 SoA arrays [200]
    float* ssc = (float*)cand;
    float* sx1 = (float*)cand + 200;
    float* sy1 = (float*)cand + 400;
    float* sx2 = (float*)cand + 600;
    float* sy2 = (float*)cand + 800;
    float* sar = (float*)cand + 1000;

    if (tid == 0) {
        cc_sh = g_ccnt[task];
        g_ccnt[task] = 0u;                // reset for next graph replay
    }
    __syncthreads();
    unsigned cc = cc_sh;

    if (cc >= (unsigned)TOPK && cc <= CANDCAP) {
        const unsigned long long* gl = g_cand + (size_t)task * CANDCAP;
        for (unsigned i = tid; i < cc; i += 256)
            cand[i] = gl[i];
    } else {
        // ---- fallback (≈never): lean two-pass softmax recompute ----
        unsigned* fb = g_fb + (size_t)task * NANCH;
#pragma unroll 1
        for (int n = tid; n < NANCH; n += 256) {
            const float* cp = conf + ((size_t)b * NANCH + n) * NCLS;
            float mx = -1e30f;
#pragma unroll 1
            for (int q = 0; q < NCLS; q++) mx = fmaxf(mx, __ldg(cp + q));
            float sum = 0.f;
#pragma unroll 1
            for (int q = 0; q < NCLS; q++) sum += expf(__ldg(cp + q) - mx);
            float p = expf(__ldg(cp + c + 1) - mx) / sum;
            fb[n] = (p > CONF_TH) ? __float_as_uint(p) : 0u;
        }
        __syncthreads();
        unsigned lo = 0u, hi = 0x3F800001u, T = T0BITS;
#pragma unroll 1
        for (int attempt = 0; attempt < 24; attempt++) {
            if (tid == 0) ccnt = 0u;
            __syncthreads();
#pragma unroll 1
            for (int n0 = 0; n0 < NANCH; n0 += 256) {
                int n = n0 + tid;
                unsigned u = (n < NANCH) ? fb[n] : 0u;
                bool pred = (u >= T);
                unsigned mask = __ballot_sync(0xffffffffu, pred);
                if (mask) {
                    int leader = __ffs(mask) - 1;
                    unsigned basev = 0u;
                    if (lane == leader) basev = atomicAdd(&ccnt, (unsigned)__popc(mask));
                    basev = __shfl_sync(0xffffffffu, basev, leader);
                    if (pred) {
                        unsigned pos = basev + (unsigned)__popc(mask & ((1u << lane) - 1u));
                        if (pos < CANDCAP)
                            cand[pos] = ((unsigned long long)u << 32) | (unsigned)(~n);
                    }
                }
            }
            __syncthreads();
            cc = ccnt;
            if (cc <= CANDCAP && (cc >= (unsigned)TOPK || T <= 1u)) break;
            if (cc > CANDCAP) lo = T; else hi = T;
            if (hi <= lo + 1u) { T = (lo > 0u) ? lo : 1u; continue; }
            T = lo + ((hi - lo) >> 1);
            if (T == 0u) T = 1u;
        }
        if (cc > CANDCAP) cc = CANDCAP;
    }

    // ---- 3-pass radix select over the list ----
    shist[tid] = 0u;
    if (tid == 0) { k_sh = TOPK; bin_sh = 0u; }
    __syncthreads();

    unsigned prefix = 0u, pmask = 0u, bin0 = 0u;
#pragma unroll
    for (int pass = 0; pass < 3; pass++) {
        const int shift = (pass == 0) ? 19 : (pass == 1) ? 11 : 3;
        for (unsigned i = tid; i < cc; i += 256) {
            unsigned u = (unsigned)(cand[i] >> 32);
            if ((u & pmask) == prefix) atomicAdd(&shist[(u >> shift) & 255u], 1u);
        }
        __syncthreads();
        if (tid < 32) {
            uint4 h0 = ((const uint4*)shist)[tid * 2];
            uint4 h1 = ((const uint4*)shist)[tid * 2 + 1];
            unsigned local[8] = {h0.x, h0.y, h0.z, h0.w, h1.x, h1.y, h1.z, h1.w};
            unsigned lsum = 0;
#pragma unroll
            for (int j = 0; j < 8; j++) lsum += local[j];
            unsigned ssum = lsum;
#pragma unroll
            for (int off = 1; off < 32; off <<= 1) {
                unsigned vv = __shfl_down_sync(0xffffffffu, ssum, off);
                if (tid + off < 32) ssum += vv;
            }
            unsigned k = k_sh;
            unsigned run = ssum - lsum;
            unsigned fbin = 0u, fk = 0u;
#pragma unroll
            for (int j = 7; j >= 0; j--) {
                unsigned prev = run;
                run += local[j];
                if (run >= k && prev < k) { fbin = (unsigned)(tid * 8 + j); fk = k - prev; }
            }
            unsigned bmax = __reduce_max_sync(0xffffffffu, fbin);
            unsigned kmax = __reduce_max_sync(0xffffffffu, fk);
            if (tid == 0) {
                bin_sh = bmax;
                if (kmax) k_sh = kmax;
            }
        }
        __syncthreads();
        unsigned bin = bin_sh;
        if (pass == 0) bin0 = bin;
        prefix |= bin << shift;
        pmask  |= 255u << shift;
        shist[tid] = 0u;
        __syncthreads();
    }
    unsigned Plo = 0x38000000u | prefix;
    if (bin0 == 0u) Plo = 1u;               // degenerate: <TOPK entries

    // ---- collect u >= Plo into skey (<=256 incl. slack ties) ----
    skey[tid] = 0ULL;
    if (tid == 0) scnt = 0u;
    __syncthreads();
    unsigned ccPad = (cc + 255u) & ~255u;
    for (unsigned i = tid; i < ccPad; i += 256) {
        unsigned long long kk = (i < cc) ? cand[i] : 0ULL;
        bool pred = ((unsigned)(kk >> 32) >= Plo);
        unsigned mask = __ballot_sync(0xffffffffu, pred);
        if (mask) {
            int leader = __ffs(mask) - 1;
            unsigned basev = 0u;
            if (lane == leader) basev = atomicAdd(&scnt, (unsigned)__popc(mask));
            basev = __shfl_sync(0xffffffffu, basev, leader);
            if (pred) {
                unsigned pos = basev + (unsigned)__popc(mask & ((1u << lane) - 1u));
                if (pos < 256u) skey[pos] = kk;
            }
        }
    }
    __syncthreads();

    // ---- bitonic sort 256 keys descending (value desc, idx asc) ----
    unsigned long long key = skey[tid];
#pragma unroll
    for (int ks = 2; ks <= 256; ks <<= 1) {
#pragma unroll
        for (int st = ks >> 1; st > 0; st <<= 0, st >>= 1) {
            bool up = ((tid & ks) == 0);
            unsigned long long other;
            if (st >= 32) {
                skey[tid] = key;
                __syncthreads();
                other = skey[tid ^ st];
                __syncthreads();
            } else {
                other = __shfl_xor_sync(0xffffffffu, key, st);
            }
            bool iLow = ((tid & st) == 0);
            bool takeMax = (iLow == up);
            bool otherBigger = (other > key);
            if (takeMax == otherBigger) key = other;
        }
    }

    // ---- fetch: ON-DEMAND box decode (bit-identical expression) ----
    if (tid < TOPK) {
        float score = 0.f, x1 = 0.f, y1 = 0.f, x2 = -1.f, y2 = -1.f, area = 0.f;
        unsigned vb = (unsigned)(key >> 32);
        if (vb != 0u) {
            unsigned n = ~(unsigned)(key & 0xFFFFFFFFu);
            score = __uint_as_float(vb);
            float4 l4 = __ldg((const float4*)loc + (size_t)b * NANCH + n);
            float4 a4 = __ldg((const float4*)anchors + n);
            float cx = a4.x + l4.x * 0.1f * a4.z;
            float cy = a4.y + l4.y * 0.1f * a4.w;
            float w  = a4.z * expf(l4.z * 0.2f);
            float h  = a4.w * expf(l4.w * 0.2f);
            x1 = cx - 0.5f * w;
            y1 = cy - 0.5f * h;
            x2 = cx + 0.5f * w;
            y2 = cy + 0.5f * h;
            area = (x2 - x1) * (y2 - y1);
        }
        ssc[tid] = score;
        sx1[tid] = x1; sy1[tid] = y1;
        sx2[tid] = x2; sy2[tid] = y2;
        sar[tid] = area;
    }
    __syncthreads();
    if (wrp != 0) return;                  // free 7 warps; warp 0 finishes

    // ---- warp-0 register NMS (shfl pivot broadcast) + pack ----
    float x1[7], y1[7], x2[7], y2[7], ar[7], sc[7];
    unsigned keep[7];
#pragma unroll
    for (int t = 0; t < 7; t++) {
        int j = t * 32 + lane;
        bool valid = (j < TOPK);
        sc[t] = valid ? ssc[j] : 0.f;
        x1[t] = valid ? sx1[j] : 0.f;
        y1[t] = valid ? sy1[j] : 0.f;
        x2[t] = valid ? sx2[j] : -1.f;
        y2[t] = valid ? sy2[j] : -1.f;
        ar[t] = valid ? sar[j] : 0.f;
        keep[t] = __ballot_sync(0xffffffffu, sc[t] > 0.f);
    }

    for (int t = 0; t < 7; t++) {
        unsigned rem = keep[t];
        while (rem) {
            int bpos = __ffs(rem) - 1;
            float px1 = __shfl_sync(0xffffffffu, x1[t], bpos);
            float py1 = __shfl_sync(0xffffffffu, y1[t], bpos);
            float px2 = __shfl_sync(0xffffffffu, x2[t], bpos);
            float py2 = __shfl_sync(0xffffffffu, y2[t], bpos);
            float pa  = __shfl_sync(0xffffffffu, ar[t], bpos);
#pragma unroll
            for (int tt = 0; tt < 7; tt++) {
                if (tt >= t && keep[tt]) {          // warp-uniform skip
                    float ix1 = fmaxf(px1, x1[tt]);
                    float iy1 = fmaxf(py1, y1[tt]);
                    float ix2 = fminf(px2, x2[tt]);
                    float iy2 = fminf(py2, y2[tt]);
                    float iw = fmaxf(ix2 - ix1, 0.0f);
                    float ih = fmaxf(iy2 - iy1, 0.0f);
                    float inter = iw * ih;
                    float iou = inter / (pa + ar[tt] - inter + 1e-12f);
                    unsigned sup = __ballot_sync(0xffffffffu, iou > NMS_TH);
                    if (tt == t) sup &= ~((2u << bpos) - 1u);   // only bits > bpos
                    keep[tt] &= ~sup;
                }
            }
            rem = keep[t] & ~((2u << bpos) - 1u);
        }
    }

    int before = 0;
#pragma unroll
    for (int t = 0; t < 7; t++) {
        if ((keep[t] >> lane) & 1u) {
            int pos = before + __popc(keep[t] & ((1u << lane) - 1u));
            float* orow = out + ((((size_t)b * NCLS + (c + 1)) * TOPK) + pos) * 5;
            orow[0] = sc[t];
            orow[1] = x1[t]; orow[2] = y1[t];
            orow[3] = x2[t]; orow[4] = y2[t];
        }
        before += __popc(keep[t]);
    }
}

// ---------------------------------------------------------------------------
extern "C" void kernel_launch(void* const* d_in, const int* in_sizes, int n_in,
                              void* d_out, int out_size) {
    const float* loc     = (const float*)d_in[0];  // [B,N,4]
    const float* conf    = (const float*)d_in[1];  // [B,N,21]
    const float* anchors = (const float*)d_in[2];  // [N,4]
    float* out = (float*)d_out;                    // [B,21,200,5]

    int total = in_sizes[0] / 4;          // B*N
    int B = total / NANCH;
    if (B > MAXB) B = MAXB;

    cudaMemsetAsync(d_out, 0, (size_t)out_size * sizeof(float), 0);

    dim3 gridA(NBLK, B);
    softmax_cand_kernel<<<gridA, 256>>>(conf);
    int ntask = B * (NCLS - 1);
    select_nms_kernel<<<ntask, 256>>>(conf, loc, anchors, out);
}

// round 12
// speedup vs baseline: 1.5637x; 1.5637x over previous
#include <cuda_runtime.h>
#include <stdint.h>

#define NANCH 8732
#define NCLS 21
#define TOPK 200
#define CONF_TH 0.01f
#define NMS_TH 0.045f
#define MAXB 128
#define CANDCAP 2048u
#define NTASKMAX (MAXB * (NCLS - 1))
#define T0BITS 0x3E000000u    // 0.125f
#define NBLK 35               // ceil(8732/256) anchor-blocks per image
#define LCAP 64               // per-CTA per-class smem list capacity

// Scratch (no device allocs allowed):
__device__ unsigned long long g_cand[(size_t)NTASKMAX * CANDCAP];     // per-task lists
__device__ unsigned g_ccnt[NTASKMAX];                                 // counts (zero-init; B1 resets)
__device__ unsigned g_fb[(size_t)NTASKMAX * NANCH];                   // fallback scratch
// sorted top-200 SoA planes [task][200]:
__device__ float g_tsc[(size_t)NTASKMAX * TOPK];
__device__ float g_tx1[(size_t)NTASKMAX * TOPK];
__device__ float g_ty1[(size_t)NTASKMAX * TOPK];
__device__ float g_tx2[(size_t)NTASKMAX * TOPK];
__device__ float g_ty2[(size_t)NTASKMAX * TOPK];
__device__ float g_tar[(size_t)NTASKMAX * TOPK];

// ---------------------------------------------------------------------------
// Kernel A: softmax + smem-aggregated candidate append (v[c] >= 0.1249*sum,
// strict superset of p >= 0.125; exact p bits stored). NO box decode.
// Grid: (NBLK, B). Flush = 1 global atomic per class per CTA.
// ---------------------------------------------------------------------------
__global__ void __launch_bounds__(256) softmax_cand_kernel(
        const float* __restrict__ conf) {
    __shared__ float sc[256 * NCLS];                         // 21504 B
    __shared__ unsigned long long slist[NCLS - 1][LCAP];     // 10240 B
    __shared__ unsigned scnt_s[NCLS - 1];

    int b = blockIdx.y;
    int n0 = blockIdx.x * 256;
    int n = n0 + threadIdx.x;
    int tid = threadIdx.x;

    if (tid < NCLS - 1) scnt_s[tid] = 0u;

    int nanch_here = min(256, NANCH - n0);
    int navail = nanch_here * NCLS;
    size_t gbase = ((size_t)b * NANCH + n0) * NCLS;
    for (int i = tid; i < navail; i += 256)
        sc[i] = conf[gbase + i];
    __syncthreads();

    if (n < NANCH) {
        float v[NCLS];
        float mx = -1e30f;
#pragma unroll
        for (int c = 0; c < NCLS; c++) { v[c] = sc[tid * NCLS + c]; mx = fmaxf(mx, v[c]); }
        float s = 0.0f;
#pragma unroll
        for (int c = 0; c < NCLS; c++) { v[c] = expf(v[c] - mx); s += v[c]; }
        float inv = 1.0f / s;
        float Ts = 0.1249f * s;            // margin 8e-4 >> fp rounding

        unsigned enc = (unsigned)(~n);
#pragma unroll
        for (int c = 1; c < NCLS; c++) {
            if (v[c] >= Ts) {
                float p = v[c] * inv;      // exact score bits
                unsigned long long key =
                    ((unsigned long long)__float_as_uint(p) << 32) | enc;
                unsigned pos = atomicAdd(&scnt_s[c - 1], 1u);
                if (pos < LCAP) {
                    slist[c - 1][pos] = key;
                } else {                   // spill (≈never): direct global
                    int task = b * (NCLS - 1) + (c - 1);
                    unsigned gp = atomicAdd(&g_ccnt[task], 1u);
                    if (gp < CANDCAP) g_cand[(size_t)task * CANDCAP + gp] = key;
                }
            }
        }
    }
    __syncthreads();

    int lane = tid & 31, wrp = tid >> 5;
    for (int cl = wrp; cl < NCLS - 1; cl += 8) {
        unsigned cnt = min(scnt_s[cl], (unsigned)LCAP);
        int task = b * (NCLS - 1) + cl;
        unsigned basep = 0u;
        if (lane == 0 && cnt) basep = atomicAdd(&g_ccnt[task], cnt);
        basep = __shfl_sync(0xffffffffu, basep, 0);
        for (unsigned i = lane; i < cnt; i += 32) {
            unsigned gp = basep + i;
            if (gp < CANDCAP) g_cand[(size_t)task * CANDCAP + gp] = slist[cl][i];
        }
    }
}

// ---------------------------------------------------------------------------
// Kernel B1 (select): ONE task per CTA. Load cand list (fallback: lean
// recompute + adaptive collect), 3-pass radix select (bits [26:19],[18:11],
// [10:3]; bits[31:27]=00111 for p in (0.01,1]), exact 256-key bitonic sort,
// ON-DEMAND box decode, write SoA planes. Resets g_ccnt[task].
// ---------------------------------------------------------------------------
__global__ void __launch_bounds__(256) select_kernel(
        const float* __restrict__ conf,
        const float* __restrict__ loc,
        const float* __restrict__ anchors) {
    int task = blockIdx.x;
    int b = task / (NCLS - 1);
    int c = task % (NCLS - 1);            // 0..19 -> class c+1
    int tid = threadIdx.x;
    int lane = tid & 31;

    __shared__ __align__(16) unsigned long long cand[CANDCAP];   // 16384 B
    __shared__ __align__(16) unsigned long long skey[256];       // 2048 B
    __shared__ __align__(16) unsigned shist[256];                // 1024 B
    __shared__ unsigned k_sh, bin_sh, ccnt, scnt, cc_sh;

    if (tid == 0) {
        cc_sh = g_ccnt[task];
        g_ccnt[task] = 0u;                // reset for next graph replay
    }
    __syncthreads();
    unsigned cc = cc_sh;

    if (cc >= (unsigned)TOPK && cc <= CANDCAP) {
        const unsigned long long* gl = g_cand + (size_t)task * CANDCAP;
        for (unsigned i = tid; i < cc; i += 256)
            cand[i] = gl[i];
    } else {
        // ---- fallback (≈never): lean two-pass softmax recompute ----
        unsigned* fb = g_fb + (size_t)task * NANCH;
#pragma unroll 1
        for (int n = tid; n < NANCH; n += 256) {
            const float* cp = conf + ((size_t)b * NANCH + n) * NCLS;
            float mx = -1e30f;
#pragma unroll 1
            for (int q = 0; q < NCLS; q++) mx = fmaxf(mx, __ldg(cp + q));
            float sum = 0.f;
#pragma unroll 1
            for (int q = 0; q < NCLS; q++) sum += expf(__ldg(cp + q) - mx);
            float p = expf(__ldg(cp + c + 1) - mx) / sum;
            fb[n] = (p > CONF_TH) ? __float_as_uint(p) : 0u;
        }
        __syncthreads();
        unsigned lo = 0u, hi = 0x3F800001u, T = T0BITS;
#pragma unroll 1
        for (int attempt = 0; attempt < 24; attempt++) {
            if (tid == 0) ccnt = 0u;
            __syncthreads();
#pragma unroll 1
            for (int n0 = 0; n0 < NANCH; n0 += 256) {
                int n = n0 + tid;
                unsigned u = (n < NANCH) ? fb[n] : 0u;
                bool pred = (u >= T);
                unsigned mask = __ballot_sync(0xffffffffu, pred);
                if (mask) {
                    int leader = __ffs(mask) - 1;
                    unsigned basev = 0u;
                    if (lane == leader) basev = atomicAdd(&ccnt, (unsigned)__popc(mask));
                    basev = __shfl_sync(0xffffffffu, basev, leader);
                    if (pred) {
                        unsigned pos = basev + (unsigned)__popc(mask & ((1u << lane) - 1u));
                        if (pos < CANDCAP)
                            cand[pos] = ((unsigned long long)u << 32) | (unsigned)(~n);
                    }
                }
            }
            __syncthreads();
            cc = ccnt;
            if (cc <= CANDCAP && (cc >= (unsigned)TOPK || T <= 1u)) break;
            if (cc > CANDCAP) lo = T; else hi = T;
            if (hi <= lo + 1u) { T = (lo > 0u) ? lo : 1u; continue; }
            T = lo + ((hi - lo) >> 1);
            if (T == 0u) T = 1u;
        }
        if (cc > CANDCAP) cc = CANDCAP;
    }

    // ---- 3-pass radix select over the list ----
    shist[tid] = 0u;
    if (tid == 0) { k_sh = TOPK; bin_sh = 0u; }
    __syncthreads();

    unsigned prefix = 0u, pmask = 0u, bin0 = 0u;
#pragma unroll
    for (int pass = 0; pass < 3; pass++) {
        const int shift = (pass == 0) ? 19 : (pass == 1) ? 11 : 3;
        for (unsigned i = tid; i < cc; i += 256) {
            unsigned u = (unsigned)(cand[i] >> 32);
            if ((u & pmask) == prefix) atomicAdd(&shist[(u >> shift) & 255u], 1u);
        }
        __syncthreads();
        if (tid < 32) {
            uint4 h0 = ((const uint4*)shist)[tid * 2];
            uint4 h1 = ((const uint4*)shist)[tid * 2 + 1];
            unsigned local[8] = {h0.x, h0.y, h0.z, h0.w, h1.x, h1.y, h1.z, h1.w};
            unsigned lsum = 0;
#pragma unroll
            for (int j = 0; j < 8; j++) lsum += local[j];
            unsigned ssum = lsum;
#pragma unroll
            for (int off = 1; off < 32; off <<= 1) {
                unsigned vv = __shfl_down_sync(0xffffffffu, ssum, off);
                if (tid + off < 32) ssum += vv;
            }
            unsigned k = k_sh;
            unsigned run = ssum - lsum;
            unsigned fbin = 0u, fk = 0u;
#pragma unroll
            for (int j = 7; j >= 0; j--) {
                unsigned prev = run;
                run += local[j];
                if (run >= k && prev < k) { fbin = (unsigned)(tid * 8 + j); fk = k - prev; }
            }
            unsigned bmax = __reduce_max_sync(0xffffffffu, fbin);
            unsigned kmax = __reduce_max_sync(0xffffffffu, fk);
            if (tid == 0) {
                bin_sh = bmax;
                if (kmax) k_sh = kmax;
            }
        }
        __syncthreads();
        unsigned bin = bin_sh;
        if (pass == 0) bin0 = bin;
        prefix |= bin << shift;
        pmask  |= 255u << shift;
        shist[tid] = 0u;
        __syncthreads();
    }
    unsigned Plo = 0x38000000u | prefix;
    if (bin0 == 0u) Plo = 1u;               // degenerate: <TOPK entries

    // ---- collect u >= Plo into skey (<=256 incl. slack ties) ----
    skey[tid] = 0ULL;
    if (tid == 0) scnt = 0u;
    __syncthreads();
    unsigned ccPad = (cc + 255u) & ~255u;
    for (unsigned i = tid; i < ccPad; i += 256) {
        unsigned long long kk = (i < cc) ? cand[i] : 0ULL;
        bool pred = ((unsigned)(kk >> 32) >= Plo);
        unsigned mask = __ballot_sync(0xffffffffu, pred);
        if (mask) {
            int leader = __ffs(mask) - 1;
            unsigned basev = 0u;
            if (lane == leader) basev = atomicAdd(&scnt, (unsigned)__popc(mask));
            basev = __shfl_sync(0xffffffffu, basev, leader);
            if (pred) {
                unsigned pos = basev + (unsigned)__popc(mask & ((1u << lane) - 1u));
                if (pos < 256u) skey[pos] = kk;
            }
        }
    }
    __syncthreads();

    // ---- bitonic sort 256 keys descending (value desc, idx asc) ----
    unsigned long long key = skey[tid];
#pragma unroll
    for (int ks = 2; ks <= 256; ks <<= 1) {
#pragma unroll
        for (int st = ks >> 1; st > 0; st >>= 1) {
            bool up = ((tid & ks) == 0);
            unsigned long long other;
            if (st >= 32) {
                skey[tid] = key;
                __syncthreads();
                other = skey[tid ^ st];
                __syncthreads();
            } else {
                other = __shfl_xor_sync(0xffffffffu, key, st);
            }
            bool iLow = ((tid & st) == 0);
            bool takeMax = (iLow == up);
            bool otherBigger = (other > key);
            if (takeMax == otherBigger) key = other;
        }
    }

    // ---- on-demand box decode (bit-identical) + write SoA planes ----
    if (tid < TOPK) {
        float score = 0.f, x1 = 0.f, y1 = 0.f, x2 = -1.f, y2 = -1.f, area = 0.f;
        unsigned vb = (unsigned)(key >> 32);
        if (vb != 0u) {
            unsigned n = ~(unsigned)(key & 0xFFFFFFFFu);
            score = __uint_as_float(vb);
            float4 l4 = __ldg((const float4*)loc + (size_t)b * NANCH + n);
            float4 a4 = __ldg((const float4*)anchors + n);
            float cx = a4.x + l4.x * 0.1f * a4.z;
            float cy = a4.y + l4.y * 0.1f * a4.w;
            float w  = a4.z * expf(l4.z * 0.2f);
            float h  = a4.w * expf(l4.w * 0.2f);
            x1 = cx - 0.5f * w;
            y1 = cy - 0.5f * h;
            x2 = cx + 0.5f * w;
            y2 = cy + 0.5f * h;
            area = (x2 - x1) * (y2 - y1);
        }
        size_t o = (size_t)task * TOPK + tid;
        g_tsc[o] = score;
        g_tx1[o] = x1; g_ty1[o] = y1;
        g_tx2[o] = x2; g_ty2[o] = y2;
        g_tar[o] = area;
    }
}

// ---------------------------------------------------------------------------
// Kernel B2 (NMS + pack): ONE WARP per task, 8 warps/CTA. Boxes cached in
// registers (7 chunks/lane), pivot broadcast via shfl, bitmask keep chain.
// ---------------------------------------------------------------------------
__global__ void __launch_bounds__(256) nms_pack_kernel(float* __restrict__ out,
                                                       int ntask) {
    int tid = threadIdx.x;
    int lane = tid & 31, wrp = tid >> 5;
    int task = blockIdx.x * 8 + wrp;
    if (task >= ntask) return;
    int b = task / (NCLS - 1);
    int c = task % (NCLS - 1);

    size_t base = (size_t)task * TOPK;
    float x1[7], y1[7], x2[7], y2[7], ar[7], sc[7];
    unsigned keep[7];
#pragma unroll
    for (int t = 0; t < 7; t++) {
        int j = t * 32 + lane;
        bool valid = (j < TOPK);
        float s_ = valid ? g_tsc[base + j] : 0.f;
        sc[t] = s_;
        x1[t] = valid ? g_tx1[base + j] : 0.f;
        y1[t] = valid ? g_ty1[base + j] : 0.f;
        x2[t] = valid ? g_tx2[base + j] : -1.f;
        y2[t] = valid ? g_ty2[base + j] : -1.f;
        ar[t] = valid ? g_tar[base + j] : 0.f;
        keep[t] = __ballot_sync(0xffffffffu, s_ > 0.f);
    }

    for (int t = 0; t < 7; t++) {
        unsigned rem = keep[t];
        while (rem) {
            int bpos = __ffs(rem) - 1;
            float px1 = __shfl_sync(0xffffffffu, x1[t], bpos);
            float py1 = __shfl_sync(0xffffffffu, y1[t], bpos);
            float px2 = __shfl_sync(0xffffffffu, x2[t], bpos);
            float py2 = __shfl_sync(0xffffffffu, y2[t], bpos);
            float pa  = __shfl_sync(0xffffffffu, ar[t], bpos);
#pragma unroll
            for (int tt = 0; tt < 7; tt++) {
                if (tt >= t && keep[tt]) {          // warp-uniform skip
                    float ix1 = fmaxf(px1, x1[tt]);
                    float iy1 = fmaxf(py1, y1[tt]);
                    float ix2 = fminf(px2, x2[tt]);
                    float iy2 = fminf(py2, y2[tt]);
                    float iw = fmaxf(ix2 - ix1, 0.0f);
                    float ih = fmaxf(iy2 - iy1, 0.0f);
                    float inter = iw * ih;
                    float iou = inter / (pa + ar[tt] - inter + 1e-12f);
                    unsigned sup = __ballot_sync(0xffffffffu, iou > NMS_TH);
                    if (tt == t) sup &= ~((2u << bpos) - 1u);   // only bits > bpos
                    keep[tt] &= ~sup;
                }
            }
            rem = keep[t] & ~((2u << bpos) - 1u);
        }
    }

    int before = 0;
#pragma unroll
    for (int t = 0; t < 7; t++) {
        if ((keep[t] >> lane) & 1u) {
            int pos = before + __popc(keep[t] & ((1u << lane) - 1u));
            float* orow = out + ((((size_t)b * NCLS + (c + 1)) * TOPK) + pos) * 5;
            orow[0] = sc[t];
            orow[1] = x1[t]; orow[2] = y1[t];
            orow[3] = x2[t]; orow[4] = y2[t];
        }
        before += __popc(keep[t]);
    }
}

// ---------------------------------------------------------------------------
extern "C" void kernel_launch(void* const* d_in, const int* in_sizes, int n_in,
                              void* d_out, int out_size) {
    const float* loc     = (const float*)d_in[0];  // [B,N,4]
    const float* conf    = (const float*)d_in[1];  // [B,N,21]
    const float* anchors = (const float*)d_in[2];  // [N,4]
    float* out = (float*)d_out;                    // [B,21,200,5]

    int total = in_sizes[0] / 4;          // B*N
    int B = total / NANCH;
    if (B > MAXB) B = MAXB;

    cudaMemsetAsync(d_out, 0, (size_t)out_size * sizeof(float), 0);

    dim3 gridA(NBLK, B);
    softmax_cand_kernel<<<gridA, 256>>>(conf);
    int ntask = B * (NCLS - 1);
    select_kernel<<<ntask, 256>>>(conf, loc, anchors);
    nms_pack_kernel<<<(ntask + 7) / 8, 256>>>(out, ntask);
}

// round 13
// speedup vs baseline: 1.5810x; 1.0110x over previous
#include <cuda_runtime.h>
#include <stdint.h>

#define NANCH 8732
#define NCLS 21
#define TOPK 200
#define CONF_TH 0.01f
#define NMS_TH 0.045f
#define MAXB 128
#define CANDCAP 2048u
#define NTASKMAX (MAXB * (NCLS - 1))
#define T0BITS 0x3E000000u    // 0.125f
#define NBLK 35               // ceil(8732/256) anchor-blocks per image
#define LCAP 64               // per-CTA per-class smem list capacity

// Scratch (no device allocs allowed):
__device__ unsigned long long g_cand[(size_t)NTASKMAX * CANDCAP];     // per-task lists
__device__ unsigned g_ccnt[NTASKMAX];                                 // counts (zero-init; B1 resets)
__device__ unsigned g_fb[(size_t)NTASKMAX * NANCH];                   // fallback scratch
// sorted top-200 SoA planes [task][200]:
__device__ float g_tsc[(size_t)NTASKMAX * TOPK];
__device__ float g_tx1[(size_t)NTASKMAX * TOPK];
__device__ float g_ty1[(size_t)NTASKMAX * TOPK];
__device__ float g_tx2[(size_t)NTASKMAX * TOPK];
__device__ float g_ty2[(size_t)NTASKMAX * TOPK];
__device__ float g_tar[(size_t)NTASKMAX * TOPK];

// ---------------------------------------------------------------------------
// Kernel A: softmax + smem-aggregated candidate append (v[c] >= 0.1249*sum,
// strict superset of p >= 0.125; exact p bits stored). NO box decode.
// ---------------------------------------------------------------------------
__global__ void __launch_bounds__(256) softmax_cand_kernel(
        const float* __restrict__ conf) {
    __shared__ float sc[256 * NCLS];                         // 21504 B
    __shared__ unsigned long long slist[NCLS - 1][LCAP];     // 10240 B
    __shared__ unsigned scnt_s[NCLS - 1];

    int b = blockIdx.y;
    int n0 = blockIdx.x * 256;
    int n = n0 + threadIdx.x;
    int tid = threadIdx.x;

    if (tid < NCLS - 1) scnt_s[tid] = 0u;

    int nanch_here = min(256, NANCH - n0);
    int navail = nanch_here * NCLS;
    size_t gbase = ((size_t)b * NANCH + n0) * NCLS;
    for (int i = tid; i < navail; i += 256)
        sc[i] = conf[gbase + i];
    __syncthreads();

    if (n < NANCH) {
        float v[NCLS];
        float mx = -1e30f;
#pragma unroll
        for (int c = 0; c < NCLS; c++) { v[c] = sc[tid * NCLS + c]; mx = fmaxf(mx, v[c]); }
        float s = 0.0f;
#pragma unroll
        for (int c = 0; c < NCLS; c++) { v[c] = expf(v[c] - mx); s += v[c]; }
        float inv = 1.0f / s;
        float Ts = 0.1249f * s;            // margin 8e-4 >> fp rounding

        unsigned enc = (unsigned)(~n);
#pragma unroll
        for (int c = 1; c < NCLS; c++) {
            if (v[c] >= Ts) {
                float p = v[c] * inv;      // exact score bits
                unsigned long long key =
                    ((unsigned long long)__float_as_uint(p) << 32) | enc;
                unsigned pos = atomicAdd(&scnt_s[c - 1], 1u);
                if (pos < LCAP) {
                    slist[c - 1][pos] = key;
                } else {                   // spill (≈never): direct global
                    int task = b * (NCLS - 1) + (c - 1);
                    unsigned gp = atomicAdd(&g_ccnt[task], 1u);
                    if (gp < CANDCAP) g_cand[(size_t)task * CANDCAP + gp] = key;
                }
            }
        }
    }
    __syncthreads();

    int lane = tid & 31, wrp = tid >> 5;
    for (int cl = wrp; cl < NCLS - 1; cl += 8) {
        unsigned cnt = min(scnt_s[cl], (unsigned)LCAP);
        int task = b * (NCLS - 1) + cl;
        unsigned basep = 0u;
        if (lane == 0 && cnt) basep = atomicAdd(&g_ccnt[task], cnt);
        basep = __shfl_sync(0xffffffffu, basep, 0);
        for (unsigned i = lane; i < cnt; i += 32) {
            unsigned gp = basep + i;
            if (gp < CANDCAP) g_cand[(size_t)task * CANDCAP + gp] = slist[cl][i];
        }
    }
}

// ---------------------------------------------------------------------------
// fold/select over a 256-bin shared histogram. Warp 0 computes, all sync.
// Writes bin_sh (pivot bin), cbin_sh (its population), updates k_sh.
// ---------------------------------------------------------------------------
__device__ __forceinline__ void fold256(unsigned* shist, unsigned* k_sh,
                                        unsigned* bin_sh, unsigned* cbin_sh,
                                        int tid) {
    __syncthreads();
    if (tid < 32) {
        uint4 h0 = ((const uint4*)shist)[tid * 2];
        uint4 h1 = ((const uint4*)shist)[tid * 2 + 1];
        unsigned local[8] = {h0.x, h0.y, h0.z, h0.w, h1.x, h1.y, h1.z, h1.w};
        unsigned lsum = 0;
#pragma unroll
        for (int j = 0; j < 8; j++) lsum += local[j];
        unsigned ssum = lsum;
#pragma unroll
        for (int off = 1; off < 32; off <<= 1) {
            unsigned vv = __shfl_down_sync(0xffffffffu, ssum, off);
            if (tid + off < 32) ssum += vv;
        }
        unsigned k = *k_sh;
        unsigned run = ssum - lsum;
        unsigned fbin = 0u, fk = 0u, fcnt = 0u;
#pragma unroll
        for (int j = 7; j >= 0; j--) {
            unsigned prev = run;
            run += local[j];
            if (run >= k && prev < k) {
                fbin = (unsigned)(tid * 8 + j);
                fk = k - prev;
                fcnt = local[j];
            }
        }
        unsigned bmax = __reduce_max_sync(0xffffffffu, fbin);
        unsigned kmax = __reduce_max_sync(0xffffffffu, fk);
        unsigned cmax = __reduce_max_sync(0xffffffffu, fcnt);
        if (tid == 0) {
            *bin_sh = bmax;
            *cbin_sh = cmax;
            if (kmax) *k_sh = kmax;
        }
    }
    __syncthreads();
}

// ---------------------------------------------------------------------------
// Kernel B1 (select): ONE task per CTA. Fused list-load + pass-0 histogram,
// EARLY-EXIT pivot (gt+cbin<=256 -> bin0 floor); rare fat-bin path does
// passes 1-2 (bits [18:11],[10:3]). Exact 256-key bitonic sort, on-demand
// box decode, SoA plane writes. Resets g_ccnt[task].
// ---------------------------------------------------------------------------
__global__ void __launch_bounds__(256) select_kernel(
        const float* __restrict__ conf,
        const float* __restrict__ loc,
        const float* __restrict__ anchors) {
    int task = blockIdx.x;
    int b = task / (NCLS - 1);
    int c = task % (NCLS - 1);            // 0..19 -> class c+1
    int tid = threadIdx.x;
    int lane = tid & 31;

    __shared__ __align__(16) unsigned long long cand[CANDCAP];   // 16384 B
    __shared__ __align__(16) unsigned long long skey[256];       // 2048 B
    __shared__ __align__(16) unsigned shist[256];                // 1024 B
    __shared__ unsigned k_sh, bin_sh, cbin_sh, ccnt, scnt, cc_sh;

    if (tid == 0) {
        cc_sh = g_ccnt[task];
        g_ccnt[task] = 0u;                // reset for next graph replay
    }
    shist[tid] = 0u;
    if (tid == 0) { k_sh = TOPK; bin_sh = 0u; cbin_sh = 0u; }
    __syncthreads();
    unsigned cc = cc_sh;

    if (cc >= (unsigned)TOPK && cc <= CANDCAP) {
        // ---- main path: fused list load + pass-0 histogram ----
        const unsigned long long* gl = g_cand + (size_t)task * CANDCAP;
        for (unsigned i = tid; i < cc; i += 256) {
            unsigned long long kk = gl[i];
            cand[i] = kk;
            atomicAdd(&shist[((unsigned)(kk >> 32) >> 19) & 255u], 1u);
        }
    } else {
        // ---- fallback (≈never): lean two-pass softmax recompute ----
        unsigned* fb = g_fb + (size_t)task * NANCH;
#pragma unroll 1
        for (int n = tid; n < NANCH; n += 256) {
            const float* cp = conf + ((size_t)b * NANCH + n) * NCLS;
            float mx = -1e30f;
#pragma unroll 1
            for (int q = 0; q < NCLS; q++) mx = fmaxf(mx, __ldg(cp + q));
            float sum = 0.f;
#pragma unroll 1
            for (int q = 0; q < NCLS; q++) sum += expf(__ldg(cp + q) - mx);
            float p = expf(__ldg(cp + c + 1) - mx) / sum;
            fb[n] = (p > CONF_TH) ? __float_as_uint(p) : 0u;
        }
        __syncthreads();
        unsigned lo = 0u, hi = 0x3F800001u, T = T0BITS;
#pragma unroll 1
        for (int attempt = 0; attempt < 24; attempt++) {
            if (tid == 0) ccnt = 0u;
            __syncthreads();
#pragma unroll 1
            for (int n0 = 0; n0 < NANCH; n0 += 256) {
                int n = n0 + tid;
                unsigned u = (n < NANCH) ? fb[n] : 0u;
                bool pred = (u >= T);
                unsigned mask = __ballot_sync(0xffffffffu, pred);
                if (mask) {
                    int leader = __ffs(mask) - 1;
                    unsigned basev = 0u;
                    if (lane == leader) basev = atomicAdd(&ccnt, (unsigned)__popc(mask));
                    basev = __shfl_sync(0xffffffffu, basev, leader);
                    if (pred) {
                        unsigned pos = basev + (unsigned)__popc(mask & ((1u << lane) - 1u));
                        if (pos < CANDCAP)
                            cand[pos] = ((unsigned long long)u << 32) | (unsigned)(~n);
                    }
                }
            }
            __syncthreads();
            cc = ccnt;
            if (cc <= CANDCAP && (cc >= (unsigned)TOPK || T <= 1u)) break;
            if (cc > CANDCAP) lo = T; else hi = T;
            if (hi <= lo + 1u) { T = (lo > 0u) ? lo : 1u; continue; }
            T = lo + ((hi - lo) >> 1);
            if (T == 0u) T = 1u;
        }
        if (cc > CANDCAP) cc = CANDCAP;
        // pass-0 histogram for fallback-built list
        for (unsigned i = tid; i < cc; i += 256)
            atomicAdd(&shist[((unsigned)(cand[i] >> 32) >> 19) & 255u], 1u);
    }

    // ---- pass-0 fold/select + early exit ----
    fold256(shist, &k_sh, &bin_sh, &cbin_sh, tid);
    unsigned bin0 = bin_sh;
    unsigned Plo;
    if (bin0 == 0u) {
        Plo = 1u;                          // degenerate: <TOPK entries, take all
    } else if ((unsigned)TOPK - k_sh + cbin_sh <= 256u) {
        Plo = 0x38000000u | (bin0 << 19);  // common: bin0 floor already <=256 superset
    } else {
        // rare fat-bin path: refine with passes 1-2
        unsigned prefix = bin0 << 19, pmask = 255u << 19;
#pragma unroll 1
        for (int pass = 1; pass < 3; pass++) {
            const int shift = (pass == 1) ? 11 : 3;
            shist[tid] = 0u;
            __syncthreads();
            for (unsigned i = tid; i < cc; i += 256) {
                unsigned u = (unsigned)(cand[i] >> 32);
                if ((u & pmask) == prefix) atomicAdd(&shist[(u >> shift) & 255u], 1u);
            }
            fold256(shist, &k_sh, &bin_sh, &cbin_sh, tid);
            prefix |= bin_sh << shift;
            pmask  |= 255u << shift;
        }
        Plo = 0x38000000u | prefix;
    }

    // ---- collect u >= Plo into skey (<=256 incl. slack ties) ----
    skey[tid] = 0ULL;
    if (tid == 0) scnt = 0u;
    __syncthreads();
    unsigned ccPad = (cc + 255u) & ~255u;
    for (unsigned i = tid; i < ccPad; i += 256) {
        unsigned long long kk = (i < cc) ? cand[i] : 0ULL;
        bool pred = ((unsigned)(kk >> 32) >= Plo);
        unsigned mask = __ballot_sync(0xffffffffu, pred);
        if (mask) {
            int leader = __ffs(mask) - 1;
            unsigned basev = 0u;
            if (lane == leader) basev = atomicAdd(&scnt, (unsigned)__popc(mask));
            basev = __shfl_sync(0xffffffffu, basev, leader);
            if (pred) {
                unsigned pos = basev + (unsigned)__popc(mask & ((1u << lane) - 1u));
                if (pos < 256u) skey[pos] = kk;
            }
        }
    }
    __syncthreads();

    // ---- bitonic sort 256 keys descending (value desc, idx asc) ----
    unsigned long long key = skey[tid];
#pragma unroll
    for (int ks = 2; ks <= 256; ks <<= 1) {
#pragma unroll
        for (int st = ks >> 1; st > 0; st >>= 1) {
            bool up = ((tid & ks) == 0);
            unsigned long long other;
            if (st >= 32) {
                skey[tid] = key;
                __syncthreads();
                other = skey[tid ^ st];
                __syncthreads();
            } else {
                other = __shfl_xor_sync(0xffffffffu, key, st);
            }
            bool iLow = ((tid & st) == 0);
            bool takeMax = (iLow == up);
            bool otherBigger = (other > key);
            if (takeMax == otherBigger) key = other;
        }
    }

    // ---- on-demand box decode (bit-identical) + write SoA planes ----
    if (tid < TOPK) {
        float score = 0.f, x1 = 0.f, y1 = 0.f, x2 = -1.f, y2 = -1.f, area = 0.f;
        unsigned vb = (unsigned)(key >> 32);
        if (vb != 0u) {
            unsigned n = ~(unsigned)(key & 0xFFFFFFFFu);
            score = __uint_as_float(vb);
            float4 l4 = __ldg((const float4*)loc + (size_t)b * NANCH + n);
            float4 a4 = __ldg((const float4*)anchors + n);
            float cx = a4.x + l4.x * 0.1f * a4.z;
            float cy = a4.y + l4.y * 0.1f * a4.w;
            float w  = a4.z * expf(l4.z * 0.2f);
            float h  = a4.w * expf(l4.w * 0.2f);
            x1 = cx - 0.5f * w;
            y1 = cy - 0.5f * h;
            x2 = cx + 0.5f * w;
            y2 = cy + 0.5f * h;
            area = (x2 - x1) * (y2 - y1);
        }
        size_t o = (size_t)task * TOPK + tid;
        g_tsc[o] = score;
        g_tx1[o] = x1; g_ty1[o] = y1;
        g_tx2[o] = x2; g_ty2[o] = y2;
        g_tar[o] = area;
    }
}

// ---------------------------------------------------------------------------
// Kernel B2 (NMS + pack + plane zeroing): ONE WARP per task, 8 warps/CTA.
// Zeroes its own output plane (and class-0 plane for c==0 tasks) — replaces
// the separate memset launch. Boxes cached in registers, shfl pivot bcast.
// ---------------------------------------------------------------------------
__global__ void __launch_bounds__(256) nms_pack_kernel(float* __restrict__ out,
                                                       int ntask) {
    int tid = threadIdx.x;
    int lane = tid & 31, wrp = tid >> 5;
    int task = blockIdx.x * 8 + wrp;
    if (task >= ntask) return;
    int b = task / (NCLS - 1);
    int c = task % (NCLS - 1);

    size_t base = (size_t)task * TOPK;
    float x1[7], y1[7], x2[7], y2[7], ar[7], sc[7];
    unsigned keep[7];
#pragma unroll
    for (int t = 0; t < 7; t++) {
        int j = t * 32 + lane;
        bool valid = (j < TOPK);
        float s_ = valid ? g_tsc[base + j] : 0.f;
        sc[t] = s_;
        x1[t] = valid ? g_tx1[base + j] : 0.f;
        y1[t] = valid ? g_ty1[base + j] : 0.f;
        x2[t] = valid ? g_tx2[base + j] : -1.f;
        y2[t] = valid ? g_ty2[base + j] : -1.f;
        ar[t] = valid ? g_tar[base + j] : 0.f;
        keep[t] = __ballot_sync(0xffffffffu, s_ > 0.f);
    }

    // zero this task's output plane (1000 floats = 250 float4)
    float4 z4 = make_float4(0.f, 0.f, 0.f, 0.f);
    float4* oplane = (float4*)(out + (((size_t)b * NCLS + (c + 1)) * TOPK) * 5);
#pragma unroll 1
    for (int i = lane; i < 250; i += 32) oplane[i] = z4;
    if (c == 0) {   // also zero this image's background (class 0) plane
        float4* zplane = (float4*)(out + (((size_t)b * NCLS) * TOPK) * 5);
#pragma unroll 1
        for (int i = lane; i < 250; i += 32) zplane[i] = z4;
    }
    __syncwarp();

    for (int t = 0; t < 7; t++) {
        unsigned rem = keep[t];
        while (rem) {
            int bpos = __ffs(rem) - 1;
            float px1 = __shfl_sync(0xffffffffu, x1[t], bpos);
            float py1 = __shfl_sync(0xffffffffu, y1[t], bpos);
            float px2 = __shfl_sync(0xffffffffu, x2[t], bpos);
            float py2 = __shfl_sync(0xffffffffu, y2[t], bpos);
            float pa  = __shfl_sync(0xffffffffu, ar[t], bpos);
#pragma unroll
            for (int tt = 0; tt < 7; tt++) {
                if (tt >= t && keep[tt]) {          // warp-uniform skip
                    float ix1 = fmaxf(px1, x1[tt]);
                    float iy1 = fmaxf(py1, y1[tt]);
                    float ix2 = fminf(px2, x2[tt]);
                    float iy2 = fminf(py2, y2[tt]);
                    float iw = fmaxf(ix2 - ix1, 0.0f);
                    float ih = fmaxf(iy2 - iy1, 0.0f);
                    float inter = iw * ih;
                    float iou = inter / (pa + ar[tt] - inter + 1e-12f);
                    unsigned sup = __ballot_sync(0xffffffffu, iou > NMS_TH);
                    if (tt == t) sup &= ~((2u << bpos) - 1u);   // only bits > bpos
                    keep[tt] &= ~sup;
                }
            }
            rem = keep[t] & ~((2u << bpos) - 1u);
        }
    }

    int before = 0;
#pragma unroll
    for (int t = 0; t < 7; t++) {
        if ((keep[t] >> lane) & 1u) {
            int pos = before + __popc(keep[t] & ((1u << lane) - 1u));
            float* orow = out + ((((size_t)b * NCLS + (c + 1)) * TOPK) + pos) * 5;
            orow[0] = sc[t];
            orow[1] = x1[t]; orow[2] = y1[t];
            orow[3] = x2[t]; orow[4] = y2[t];
        }
        before += __popc(keep[t]);
    }
}

// ---------------------------------------------------------------------------
extern "C" void kernel_launch(void* const* d_in, const int* in_sizes, int n_in,
                              void* d_out, int out_size) {
    const float* loc     = (const float*)d_in[0];  // [B,N,4]
    const float* conf    = (const float*)d_in[1];  // [B,N,21]
    const float* anchors = (const float*)d_in[2];  // [N,4]
    float* out = (float*)d_out;                    // [B,21,200,5]

    int total = in_sizes[0] / 4;          // B*N
    int B = total / NANCH;
    if (B > MAXB) B = MAXB;

    dim3 gridA(NBLK, B);
    softmax_cand_kernel<<<gridA, 256>>>(conf);
    int ntask = B * (NCLS - 1);
    select_kernel<<<ntask, 256>>>(conf, loc, anchors);
    nms_pack_kernel<<<(ntask + 7) / 8, 256>>>(out, ntask);
}

// round 14
// speedup vs baseline: 1.6154x; 1.0218x over previous
#include <cuda_runtime.h>
#include <stdint.h>

#define NANCH 8732
#define NCLS 21
#define TOPK 200
#define CONF_TH 0.01f
#define NMS_TH 0.045f
#define MAXB 128
#define CANDCAP 2048u
#define NTASKMAX (MAXB * (NCLS - 1))
#define T0BITS 0x3E000000u    // 0.125f
#define NBLK 35               // ceil(8732/256) anchor-blocks per image
#define LCAP 64               // per-CTA per-class smem list capacity

// Scratch (no device allocs allowed):
__device__ unsigned long long g_cand[(size_t)NTASKMAX * CANDCAP];     // per-task lists
__device__ unsigned g_ccnt[NTASKMAX];                                 // counts (zero-init; B1 resets)
__device__ unsigned g_fb[(size_t)NTASKMAX * NANCH];                   // fallback scratch
// sorted top-200 SoA planes [task][200]:
__device__ float g_tsc[(size_t)NTASKMAX * TOPK];
__device__ float g_tx1[(size_t)NTASKMAX * TOPK];
__device__ float g_ty1[(size_t)NTASKMAX * TOPK];
__device__ float g_tx2[(size_t)NTASKMAX * TOPK];
__device__ float g_ty2[(size_t)NTASKMAX * TOPK];
__device__ float g_tar[(size_t)NTASKMAX * TOPK];

// ---------------------------------------------------------------------------
// Kernel A: softmax + smem-aggregated candidate append (v[c] >= 0.1249*sum,
// strict superset of p >= 0.125; exact p bits stored). NO box decode.
// Staging copy vectorized (float4); compute order bit-identical to R13.
// ---------------------------------------------------------------------------
__global__ void __launch_bounds__(256) softmax_cand_kernel(
        const float* __restrict__ conf) {
    __shared__ __align__(16) float sc[256 * NCLS];           // 21504 B
    __shared__ unsigned long long slist[NCLS - 1][LCAP];     // 10240 B
    __shared__ unsigned scnt_s[NCLS - 1];

    int b = blockIdx.y;
    int n0 = blockIdx.x * 256;
    int n = n0 + threadIdx.x;
    int tid = threadIdx.x;

    if (tid < NCLS - 1) scnt_s[tid] = 0u;

    int nanch_here = min(256, NANCH - n0);
    int navail4 = (nanch_here * NCLS) >> 2;   // divisible by 4 for both shapes
    size_t gbase = ((size_t)b * NANCH + n0) * NCLS;  // divisible by 4 -> 16B aligned
    const float4* cf4 = (const float4*)(conf + gbase);
    float4* sc4 = (float4*)sc;
    for (int i = tid; i < navail4; i += 256)
        sc4[i] = __ldg(cf4 + i);
    __syncthreads();

    if (n < NANCH) {
        float v[NCLS];
        float mx = -1e30f;
#pragma unroll
        for (int c = 0; c < NCLS; c++) { v[c] = sc[tid * NCLS + c]; mx = fmaxf(mx, v[c]); }
        float s = 0.0f;
#pragma unroll
        for (int c = 0; c < NCLS; c++) { v[c] = expf(v[c] - mx); s += v[c]; }
        float inv = 1.0f / s;
        float Ts = 0.1249f * s;            // margin 8e-4 >> fp rounding

        unsigned enc = (unsigned)(~n);
#pragma unroll
        for (int c = 1; c < NCLS; c++) {
            if (v[c] >= Ts) {
                float p = v[c] * inv;      // exact score bits
                unsigned long long key =
                    ((unsigned long long)__float_as_uint(p) << 32) | enc;
                unsigned pos = atomicAdd(&scnt_s[c - 1], 1u);
                if (pos < LCAP) {
                    slist[c - 1][pos] = key;
                } else {                   // spill (≈never): direct global
                    int task = b * (NCLS - 1) + (c - 1);
                    unsigned gp = atomicAdd(&g_ccnt[task], 1u);
                    if (gp < CANDCAP) g_cand[(size_t)task * CANDCAP + gp] = key;
                }
            }
        }
    }
    __syncthreads();

    int lane = tid & 31, wrp = tid >> 5;
    for (int cl = wrp; cl < NCLS - 1; cl += 8) {
        unsigned cnt = min(scnt_s[cl], (unsigned)LCAP);
        int task = b * (NCLS - 1) + cl;
        unsigned basep = 0u;
        if (lane == 0 && cnt) basep = atomicAdd(&g_ccnt[task], cnt);
        basep = __shfl_sync(0xffffffffu, basep, 0);
        for (unsigned i = lane; i < cnt; i += 32) {
            unsigned gp = basep + i;
            if (gp < CANDCAP) g_cand[(size_t)task * CANDCAP + gp] = slist[cl][i];
        }
    }
}

// ---------------------------------------------------------------------------
// fold/select over a 256-bin shared histogram. Warp 0 computes, all sync.
// Writes bin_sh (pivot bin), cbin_sh (its population), updates k_sh.
// ---------------------------------------------------------------------------
__device__ __forceinline__ void fold256(unsigned* shist, unsigned* k_sh,
                                        unsigned* bin_sh, unsigned* cbin_sh,
                                        int tid) {
    __syncthreads();
    if (tid < 32) {
        uint4 h0 = ((const uint4*)shist)[tid * 2];
        uint4 h1 = ((const uint4*)shist)[tid * 2 + 1];
        unsigned local[8] = {h0.x, h0.y, h0.z, h0.w, h1.x, h1.y, h1.z, h1.w};
        unsigned lsum = 0;
#pragma unroll
        for (int j = 0; j < 8; j++) lsum += local[j];
        unsigned ssum = lsum;
#pragma unroll
        for (int off = 1; off < 32; off <<= 1) {
            unsigned vv = __shfl_down_sync(0xffffffffu, ssum, off);
            if (tid + off < 32) ssum += vv;
        }
        unsigned k = *k_sh;
        unsigned run = ssum - lsum;
        unsigned fbin = 0u, fk = 0u, fcnt = 0u;
#pragma unroll
        for (int j = 7; j >= 0; j--) {
            unsigned prev = run;
            run += local[j];
            if (run >= k && prev < k) {
                fbin = (unsigned)(tid * 8 + j);
                fk = k - prev;
                fcnt = local[j];
            }
        }
        unsigned bmax = __reduce_max_sync(0xffffffffu, fbin);
        unsigned kmax = __reduce_max_sync(0xffffffffu, fk);
        unsigned cmax = __reduce_max_sync(0xffffffffu, fcnt);
        if (tid == 0) {
            *bin_sh = bmax;
            *cbin_sh = cmax;
            if (kmax) *k_sh = kmax;
        }
    }
    __syncthreads();
}

// ---------------------------------------------------------------------------
// Kernel B1 (select): ONE task per CTA. Fused list-load + pass-0 histogram,
// EARLY-EXIT pivot (gt+cbin<=256 -> bin0 floor); rare fat-bin path does
// passes 1-2. Exact 256-key bitonic sort with DOUBLE-BUFFERED smem stages,
// on-demand box decode, SoA plane writes. Resets g_ccnt[task].
// ---------------------------------------------------------------------------
__global__ void __launch_bounds__(256) select_kernel(
        const float* __restrict__ conf,
        const float* __restrict__ loc,
        const float* __restrict__ anchors) {
    int task = blockIdx.x;
    int b = task / (NCLS - 1);
    int c = task % (NCLS - 1);            // 0..19 -> class c+1
    int tid = threadIdx.x;
    int lane = tid & 31;

    __shared__ __align__(16) unsigned long long cand[CANDCAP];   // 16384 B
    __shared__ __align__(16) unsigned long long skeyA[256];      // 2048 B
    __shared__ __align__(16) unsigned long long skeyB[256];      // 2048 B
    __shared__ __align__(16) unsigned shist[256];                // 1024 B
    __shared__ unsigned k_sh, bin_sh, cbin_sh, ccnt, scnt, cc_sh;

    if (tid == 0) {
        cc_sh = g_ccnt[task];
        g_ccnt[task] = 0u;                // reset for next graph replay
    }
    shist[tid] = 0u;
    if (tid == 0) { k_sh = TOPK; bin_sh = 0u; cbin_sh = 0u; }
    __syncthreads();
    unsigned cc = cc_sh;

    if (cc >= (unsigned)TOPK && cc <= CANDCAP) {
        // ---- main path: fused list load + pass-0 histogram ----
        const unsigned long long* gl = g_cand + (size_t)task * CANDCAP;
        for (unsigned i = tid; i < cc; i += 256) {
            unsigned long long kk = gl[i];
            cand[i] = kk;
            atomicAdd(&shist[((unsigned)(kk >> 32) >> 19) & 255u], 1u);
        }
    } else {
        // ---- fallback (≈never): lean two-pass softmax recompute ----
        unsigned* fb = g_fb + (size_t)task * NANCH;
#pragma unroll 1
        for (int n = tid; n < NANCH; n += 256) {
            const float* cp = conf + ((size_t)b * NANCH + n) * NCLS;
            float mx = -1e30f;
#pragma unroll 1
            for (int q = 0; q < NCLS; q++) mx = fmaxf(mx, __ldg(cp + q));
            float sum = 0.f;
#pragma unroll 1
            for (int q = 0; q < NCLS; q++) sum += expf(__ldg(cp + q) - mx);
            float p = expf(__ldg(cp + c + 1) - mx) / sum;
            fb[n] = (p > CONF_TH) ? __float_as_uint(p) : 0u;
        }
        __syncthreads();
        unsigned lo = 0u, hi = 0x3F800001u, T = T0BITS;
#pragma unroll 1
        for (int attempt = 0; attempt < 24; attempt++) {
            if (tid == 0) ccnt = 0u;
            __syncthreads();
#pragma unroll 1
            for (int n0 = 0; n0 < NANCH; n0 += 256) {
                int n = n0 + tid;
                unsigned u = (n < NANCH) ? fb[n] : 0u;
                if (u >= T) {
                    unsigned pos = atomicAdd(&ccnt, 1u);
                    if (pos < CANDCAP)
                        cand[pos] = ((unsigned long long)u << 32) | (unsigned)(~n);
                }
            }
            __syncthreads();
            cc = ccnt;
            if (cc <= CANDCAP && (cc >= (unsigned)TOPK || T <= 1u)) break;
            if (cc > CANDCAP) lo = T; else hi = T;
            if (hi <= lo + 1u) { T = (lo > 0u) ? lo : 1u; continue; }
            T = lo + ((hi - lo) >> 1);
            if (T == 0u) T = 1u;
        }
        if (cc > CANDCAP) cc = CANDCAP;
        // pass-0 histogram for fallback-built list
        for (unsigned i = tid; i < cc; i += 256)
            atomicAdd(&shist[((unsigned)(cand[i] >> 32) >> 19) & 255u], 1u);
    }

    // ---- pass-0 fold/select + early exit ----
    fold256(shist, &k_sh, &bin_sh, &cbin_sh, tid);
    unsigned bin0 = bin_sh;
    unsigned Plo;
    if (bin0 == 0u) {
        Plo = 1u;                          // degenerate: <TOPK entries, take all
    } else if ((unsigned)TOPK - k_sh + cbin_sh <= 256u) {
        Plo = 0x38000000u | (bin0 << 19);  // common: bin0 floor already <=256 superset
    } else {
        // rare fat-bin path: refine with passes 1-2
        unsigned prefix = bin0 << 19, pmask = 255u << 19;
#pragma unroll 1
        for (int pass = 1; pass < 3; pass++) {
            const int shift = (pass == 1) ? 11 : 3;
            shist[tid] = 0u;
            __syncthreads();
            for (unsigned i = tid; i < cc; i += 256) {
                unsigned u = (unsigned)(cand[i] >> 32);
                if ((u & pmask) == prefix) atomicAdd(&shist[(u >> shift) & 255u], 1u);
            }
            fold256(shist, &k_sh, &bin_sh, &cbin_sh, tid);
            prefix |= bin_sh << shift;
            pmask  |= 255u << shift;
        }
        Plo = 0x38000000u | prefix;
    }

    // ---- collect u >= Plo into skeyA (<=256 incl. slack ties) ----
    skeyA[tid] = 0ULL;
    if (tid == 0) scnt = 0u;
    __syncthreads();
    for (unsigned i = tid; i < cc; i += 256) {
        unsigned long long kk = cand[i];
        if ((unsigned)(kk >> 32) >= Plo) {
            unsigned pos = atomicAdd(&scnt, 1u);
            if (pos < 256u) skeyA[pos] = kk;
        }
    }
    __syncthreads();

    // ---- bitonic sort 256 keys descending (value desc, idx asc) ----
    // cross-warp stages double-buffered: one barrier per stage
    unsigned long long key = skeyA[tid];
    unsigned long long* bufs[2] = {skeyA, skeyB};
    int pb = 0;
#pragma unroll
    for (int ks = 2; ks <= 256; ks <<= 1) {
#pragma unroll
        for (int st = ks >> 1; st > 0; st >>= 1) {
            bool up = ((tid & ks) == 0);
            unsigned long long other;
            if (st >= 32) {
                unsigned long long* bw = bufs[pb];
                pb ^= 1;
                bw[tid] = key;
                __syncthreads();
                other = bw[tid ^ st];
                // no trailing barrier: next smem stage writes the other buffer
            } else {
                other = __shfl_xor_sync(0xffffffffu, key, st);
            }
            bool iLow = ((tid & st) == 0);
            bool takeMax = (iLow == up);
            bool otherBigger = (other > key);
            if (takeMax == otherBigger) key = other;
        }
    }

    // ---- on-demand box decode (bit-identical) + write SoA planes ----
    if (tid < TOPK) {
        float score = 0.f, x1 = 0.f, y1 = 0.f, x2 = -1.f, y2 = -1.f, area = 0.f;
        unsigned vb = (unsigned)(key >> 32);
        if (vb != 0u) {
            unsigned n = ~(unsigned)(key & 0xFFFFFFFFu);
            score = __uint_as_float(vb);
            float4 l4 = __ldg((const float4*)loc + (size_t)b * NANCH + n);
            float4 a4 = __ldg((const float4*)anchors + n);
            float cx = a4.x + l4.x * 0.1f * a4.z;
            float cy = a4.y + l4.y * 0.1f * a4.w;
            float w  = a4.z * expf(l4.z * 0.2f);
            float h  = a4.w * expf(l4.w * 0.2f);
            x1 = cx - 0.5f * w;
            y1 = cy - 0.5f * h;
            x2 = cx + 0.5f * w;
            y2 = cy + 0.5f * h;
            area = (x2 - x1) * (y2 - y1);
        }
        size_t o = (size_t)task * TOPK + tid;
        g_tsc[o] = score;
        g_tx1[o] = x1; g_ty1[o] = y1;
        g_tx2[o] = x2; g_ty2[o] = y2;
        g_tar[o] = area;
    }
}

// ---------------------------------------------------------------------------
// Kernel B2 (NMS + pack + plane zeroing): ONE WARP per task, 8 warps/CTA.
// Zeroes its own output plane (and class-0 plane for c==0 tasks). Boxes
// cached in registers, shfl pivot broadcast, bitmask keep chain.
// ---------------------------------------------------------------------------
__global__ void __launch_bounds__(256) nms_pack_kernel(float* __restrict__ out,
                                                       int ntask) {
    int tid = threadIdx.x;
    int lane = tid & 31, wrp = tid >> 5;
    int task = blockIdx.x * 8 + wrp;
    if (task >= ntask) return;
    int b = task / (NCLS - 1);
    int c = task % (NCLS - 1);

    size_t base = (size_t)task * TOPK;
    float x1[7], y1[7], x2[7], y2[7], ar[7], sc[7];
    unsigned keep[7];
#pragma unroll
    for (int t = 0; t < 7; t++) {
        int j = t * 32 + lane;
        bool valid = (j < TOPK);
        float s_ = valid ? g_tsc[base + j] : 0.f;
        sc[t] = s_;
        x1[t] = valid ? g_tx1[base + j] : 0.f;
        y1[t] = valid ? g_ty1[base + j] : 0.f;
        x2[t] = valid ? g_tx2[base + j] : -1.f;
        y2[t] = valid ? g_ty2[base + j] : -1.f;
        ar[t] = valid ? g_tar[base + j] : 0.f;
        keep[t] = __ballot_sync(0xffffffffu, s_ > 0.f);
    }

    // zero this task's output plane (1000 floats = 250 float4)
    float4 z4 = make_float4(0.f, 0.f, 0.f, 0.f);
    float4* oplane = (float4*)(out + (((size_t)b * NCLS + (c + 1)) * TOPK) * 5);
#pragma unroll 1
    for (int i = lane; i < 250; i += 32) oplane[i] = z4;
    if (c == 0) {   // also zero this image's background (class 0) plane
        float4* zplane = (float4*)(out + (((size_t)b * NCLS) * TOPK) * 5);
#pragma unroll 1
        for (int i = lane; i < 250; i += 32) zplane[i] = z4;
    }
    __syncwarp();

    for (int t = 0; t < 7; t++) {
        unsigned rem = keep[t];
        while (rem) {
            int bpos = __ffs(rem) - 1;
            float px1 = __shfl_sync(0xffffffffu, x1[t], bpos);
            float py1 = __shfl_sync(0xffffffffu, y1[t], bpos);
            float px2 = __shfl_sync(0xffffffffu, x2[t], bpos);
            float py2 = __shfl_sync(0xffffffffu, y2[t], bpos);
            float pa  = __shfl_sync(0xffffffffu, ar[t], bpos);
#pragma unroll
            for (int tt = 0; tt < 7; tt++) {
                if (tt >= t && keep[tt]) {          // warp-uniform skip
                    float ix1 = fmaxf(px1, x1[tt]);
                    float iy1 = fmaxf(py1, y1[tt]);
                    float ix2 = fminf(px2, x2[tt]);
                    float iy2 = fminf(py2, y2[tt]);
                    float iw = fmaxf(ix2 - ix1, 0.0f);
                    float ih = fmaxf(iy2 - iy1, 0.0f);
                    float inter = iw * ih;
                    float iou = inter / (pa + ar[tt] - inter + 1e-12f);
                    unsigned sup = __ballot_sync(0xffffffffu, iou > NMS_TH);
                    if (tt == t) sup &= ~((2u << bpos) - 1u);   // only bits > bpos
                    keep[tt] &= ~sup;
                }
            }
            rem = keep[t] & ~((2u << bpos) - 1u);
        }
    }

    int before = 0;
#pragma unroll
    for (int t = 0; t < 7; t++) {
        if ((keep[t] >> lane) & 1u) {
            int pos = before + __popc(keep[t] & ((1u << lane) - 1u));
            float* orow = out + ((((size_t)b * NCLS + (c + 1)) * TOPK) + pos) * 5;
            orow[0] = sc[t];
            orow[1] = x1[t]; orow[2] = y1[t];
            orow[3] = x2[t]; orow[4] = y2[t];
        }
        before += __popc(keep[t]);
    }
}

// ---------------------------------------------------------------------------
extern "C" void kernel_launch(void* const* d_in, const int* in_sizes, int n_in,
                              void* d_out, int out_size) {
    const float* loc     = (const float*)d_in[0];  // [B,N,4]
    const float* conf    = (const float*)d_in[1];  // [B,N,21]
    const float* anchors = (const float*)d_in[2];  // [N,4]
    float* out = (float*)d_out;                    // [B,21,200,5]

    int total = in_sizes[0] / 4;          // B*N
    int B = total / NANCH;
    if (B > MAXB) B = MAXB;

    dim3 gridA(NBLK, B);
    softmax_cand_kernel<<<gridA, 256>>>(conf);
    int ntask = B * (NCLS - 1);
    select_kernel<<<ntask, 256>>>(conf, loc, anchors);
    nms_pack_kernel<<<(ntask + 7) / 8, 256>>>(out, ntask);
}